// round 6
// baseline (speedup 1.0000x reference)
#include <cuda_runtime.h>
#include <math_constants.h>

#define N_DIM 512
#define KCH 32            // k-chunk per tile pass
#define NCHUNK (N_DIM / KCH)
#define PITCH 33          // 32 + 1 padding -> conflict-free both phases
#define WPB 8             // warps per block
#define MM_BLOCKS 2048

// Device-global scratch (no allocations allowed). Partials are fully
// overwritten by minmax_kernel every call -> no init kernel needed.
__device__ float g_pmn[MM_BLOCKS];
__device__ float g_pmx[MM_BLOCKS];
__device__ float g_mn;
__device__ float g_mx;

__global__ void minmax_kernel(const float4* __restrict__ in, long long n4) {
    float mn0 =  CUDART_INF_F, mn1 =  CUDART_INF_F;
    float mx0 = -CUDART_INF_F, mx1 = -CUDART_INF_F;
    long long stride = (long long)gridDim.x * blockDim.x;
    long long i = (long long)blockIdx.x * blockDim.x + threadIdx.x;
    // two independent accumulator pairs for MLP
    for (; i + stride < n4; i += 2 * stride) {
        float4 v0 = in[i];
        float4 v1 = in[i + stride];
        mn0 = fminf(mn0, fminf(fminf(v0.x, v0.y), fminf(v0.z, v0.w)));
        mx0 = fmaxf(mx0, fmaxf(fmaxf(v0.x, v0.y), fmaxf(v0.z, v0.w)));
        mn1 = fminf(mn1, fminf(fminf(v1.x, v1.y), fminf(v1.z, v1.w)));
        mx1 = fmaxf(mx1, fmaxf(fmaxf(v1.x, v1.y), fmaxf(v1.z, v1.w)));
    }
    if (i < n4) {
        float4 v = in[i];
        mn0 = fminf(mn0, fminf(fminf(v.x, v.y), fminf(v.z, v.w)));
        mx0 = fmaxf(mx0, fmaxf(fmaxf(v.x, v.y), fmaxf(v.z, v.w)));
    }
    float mn = fminf(mn0, mn1);
    float mx = fmaxf(mx0, mx1);
    #pragma unroll
    for (int o = 16; o > 0; o >>= 1) {
        mn = fminf(mn, __shfl_xor_sync(0xFFFFFFFFu, mn, o));
        mx = fmaxf(mx, __shfl_xor_sync(0xFFFFFFFFu, mx, o));
    }
    __shared__ float smn[32], smx[32];
    int warp = threadIdx.x >> 5;
    if ((threadIdx.x & 31) == 0) { smn[warp] = mn; smx[warp] = mx; }
    __syncthreads();
    if (threadIdx.x == 0) {
        int nwarps = (blockDim.x + 31) >> 5;
        float bmn = smn[0], bmx = smx[0];
        for (int k = 1; k < nwarps; k++) {
            bmn = fminf(bmn, smn[k]);
            bmx = fmaxf(bmx, smx[k]);
        }
        g_pmn[blockIdx.x] = bmn;   // deterministic overwrite, no atomics
        g_pmx[blockIdx.x] = bmx;
    }
}

__global__ void reduce_minmax_kernel() {
    float mn =  CUDART_INF_F;
    float mx = -CUDART_INF_F;
    for (int i = threadIdx.x; i < MM_BLOCKS; i += blockDim.x) {
        mn = fminf(mn, g_pmn[i]);
        mx = fmaxf(mx, g_pmx[i]);
    }
    #pragma unroll
    for (int o = 16; o > 0; o >>= 1) {
        mn = fminf(mn, __shfl_xor_sync(0xFFFFFFFFu, mn, o));
        mx = fmaxf(mx, __shfl_xor_sync(0xFFFFFFFFu, mx, o));
    }
    __shared__ float smn[32], smx[32];
    int warp = threadIdx.x >> 5;
    if ((threadIdx.x & 31) == 0) { smn[warp] = mn; smx[warp] = mx; }
    __syncthreads();
    if (threadIdx.x == 0) {
        int nwarps = (blockDim.x + 31) >> 5;
        float bmn = smn[0], bmx = smx[0];
        for (int k = 1; k < nwarps; k++) {
            bmn = fminf(bmn, smn[k]);
            bmx = fmaxf(bmx, smx[k]);
        }
        g_mn = bmn;
        g_mx = bmx;
    }
}

// Warp-tiled recurrence: each warp processes 32 rows; k tiled in chunks of 32.
// Global I/O is lane-per-column (coalesced); the serial step runs against a
// warp-private smem tile (pitch 33, conflict-free). Next chunk's LDGs overlap
// compute. Block order is REVERSED so the first-scheduled blocks read the tail
// of the input, which is still resident in L2 from minmax's sweep.
__global__ void __launch_bounds__(WPB * 32) recur_kernel(
        const float* __restrict__ in,
        const float* __restrict__ alpha,
        const float* __restrict__ beta,
        float* __restrict__ out,
        int rows) {
    __shared__ float tile_s[WPB][32 * PITCH];

    const int lane = threadIdx.x & 31;
    const int warp = threadIdx.x >> 5;
    const int rbid = gridDim.x - 1 - blockIdx.x;   // reverse for L2 reuse
    const int wgid = rbid * WPB + warp;
    if (wgid * 32 >= rows) return;

    float* tile = tile_s[warp];

    const float mn  = g_mn;
    const float rng = __fsub_rn(g_mx, mn);
    const float inv = __fdiv_rn(1.0f, rng);   // == div-by-rng bitwise (verified R2/R3)
    const float a   = alpha[0];
    const float nb  = -beta[0];

    const size_t base = (size_t)wgid * 32 * N_DIM;
    const float* __restrict__ inw  = in  + base;
    float* __restrict__       outw = out + base;

    // Prologue: load chunk 0 (coalesced: lane = column).
    float r[32];
    #pragma unroll
    for (int j = 0; j < 32; j++)
        r[j] = inw[(size_t)j * N_DIM + lane];

    float w = 1.0f;

    #pragma unroll 1
    for (int c = 0; c < NCHUNK; c++) {
        // Stage current chunk regs -> smem (transposed, conflict-free).
        #pragma unroll
        for (int j = 0; j < 32; j++)
            tile[j * PITCH + lane] = r[j];
        __syncwarp();

        // Issue next chunk's loads; overlap the compute below.
        if (c + 1 < NCHUNK) {
            const int k0n = (c + 1) * KCH;
            #pragma unroll
            for (int j = 0; j < 32; j++)
                r[j] = inw[(size_t)j * N_DIM + k0n + lane];
        }

        // Serial recurrence: lane = row. out[:,k] is the pre-step w.
        //   xn = (x - mn) * inv ; w' = fma(-b, xn, w + (a / w))
        #pragma unroll
        for (int kk = 0; kk < KCH; kk++) {
            float x = tile[lane * PITCH + kk];
            tile[lane * PITCH + kk] = w;
            float xn = __fmul_rn(__fsub_rn(x, mn), inv);
            w = __fmaf_rn(nb, xn, __fadd_rn(w, __fdiv_rn(a, w)));
        }
        __syncwarp();

        // Coalesced store of this chunk's w values.
        const int k0 = c * KCH;
        #pragma unroll
        for (int j = 0; j < 32; j++)
            outw[(size_t)j * N_DIM + k0 + lane] = tile[j * PITCH + lane];
        __syncwarp();
    }
}

extern "C" void kernel_launch(void* const* d_in, const int* in_sizes, int n_in,
                              void* d_out, int out_size) {
    const float* in    = (const float*)d_in[0];
    const float* alpha = (const float*)d_in[1];
    const float* beta  = (const float*)d_in[2];
    float* out = (float*)d_out;

    long long n_elems = (long long)in_sizes[0];
    long long n4 = n_elems / 4;
    int rows = (int)(n_elems / N_DIM);

    minmax_kernel<<<MM_BLOCKS, 256>>>((const float4*)in, n4);
    reduce_minmax_kernel<<<1, 256>>>();

    int warps_needed = (rows + 31) / 32;
    int blocks = (warps_needed + WPB - 1) / WPB;
    recur_kernel<<<blocks, WPB * 32>>>(in, alpha, beta, out, rows);
}

// round 7
// speedup vs baseline: 1.0025x; 1.0025x over previous
#include <cuda_runtime.h>
#include <math_constants.h>

#define N_DIM 512
#define KCH 32            // k-chunk per tile pass
#define NCHUNK (N_DIM / KCH)
#define PITCH 33          // conflict-free for both scatter and compute phases
#define WPB 8             // warps per block
#define MM_BLOCKS 2048

// Device-global scratch (no allocations allowed). Partials are fully
// overwritten by minmax_kernel every call -> no init kernel needed.
__device__ float g_pmn[MM_BLOCKS];
__device__ float g_pmx[MM_BLOCKS];
__device__ float g_mn;
__device__ float g_mx;

__global__ void minmax_kernel(const float4* __restrict__ in, long long n4) {
    float mn0 =  CUDART_INF_F, mn1 =  CUDART_INF_F;
    float mn2 =  CUDART_INF_F, mn3 =  CUDART_INF_F;
    float mx0 = -CUDART_INF_F, mx1 = -CUDART_INF_F;
    float mx2 = -CUDART_INF_F, mx3 = -CUDART_INF_F;
    long long stride = (long long)gridDim.x * blockDim.x;
    long long i = (long long)blockIdx.x * blockDim.x + threadIdx.x;
    for (; i + 3 * stride < n4; i += 4 * stride) {
        float4 v0 = in[i];
        float4 v1 = in[i + stride];
        float4 v2 = in[i + 2 * stride];
        float4 v3 = in[i + 3 * stride];
        mn0 = fminf(mn0, fminf(fminf(v0.x, v0.y), fminf(v0.z, v0.w)));
        mx0 = fmaxf(mx0, fmaxf(fmaxf(v0.x, v0.y), fmaxf(v0.z, v0.w)));
        mn1 = fminf(mn1, fminf(fminf(v1.x, v1.y), fminf(v1.z, v1.w)));
        mx1 = fmaxf(mx1, fmaxf(fmaxf(v1.x, v1.y), fmaxf(v1.z, v1.w)));
        mn2 = fminf(mn2, fminf(fminf(v2.x, v2.y), fminf(v2.z, v2.w)));
        mx2 = fmaxf(mx2, fmaxf(fmaxf(v2.x, v2.y), fmaxf(v2.z, v2.w)));
        mn3 = fminf(mn3, fminf(fminf(v3.x, v3.y), fminf(v3.z, v3.w)));
        mx3 = fmaxf(mx3, fmaxf(fmaxf(v3.x, v3.y), fmaxf(v3.z, v3.w)));
    }
    for (; i < n4; i += stride) {
        float4 v = in[i];
        mn0 = fminf(mn0, fminf(fminf(v.x, v.y), fminf(v.z, v.w)));
        mx0 = fmaxf(mx0, fmaxf(fmaxf(v.x, v.y), fmaxf(v.z, v.w)));
    }
    float mn = fminf(fminf(mn0, mn1), fminf(mn2, mn3));
    float mx = fmaxf(fmaxf(mx0, mx1), fmaxf(mx2, mx3));
    #pragma unroll
    for (int o = 16; o > 0; o >>= 1) {
        mn = fminf(mn, __shfl_xor_sync(0xFFFFFFFFu, mn, o));
        mx = fmaxf(mx, __shfl_xor_sync(0xFFFFFFFFu, mx, o));
    }
    __shared__ float smn[32], smx[32];
    int warp = threadIdx.x >> 5;
    if ((threadIdx.x & 31) == 0) { smn[warp] = mn; smx[warp] = mx; }
    __syncthreads();
    if (threadIdx.x == 0) {
        int nwarps = (blockDim.x + 31) >> 5;
        float bmn = smn[0], bmx = smx[0];
        for (int k = 1; k < nwarps; k++) {
            bmn = fminf(bmn, smn[k]);
            bmx = fmaxf(bmx, smx[k]);
        }
        g_pmn[blockIdx.x] = bmn;   // deterministic overwrite, no atomics
        g_pmx[blockIdx.x] = bmx;
    }
}

__global__ void reduce_minmax_kernel() {
    float mn =  CUDART_INF_F;
    float mx = -CUDART_INF_F;
    for (int i = threadIdx.x; i < MM_BLOCKS; i += blockDim.x) {
        mn = fminf(mn, g_pmn[i]);
        mx = fmaxf(mx, g_pmx[i]);
    }
    #pragma unroll
    for (int o = 16; o > 0; o >>= 1) {
        mn = fminf(mn, __shfl_xor_sync(0xFFFFFFFFu, mn, o));
        mx = fmaxf(mx, __shfl_xor_sync(0xFFFFFFFFu, mx, o));
    }
    __shared__ float smn[32], smx[32];
    int warp = threadIdx.x >> 5;
    if ((threadIdx.x & 31) == 0) { smn[warp] = mn; smx[warp] = mx; }
    __syncthreads();
    if (threadIdx.x == 0) {
        int nwarps = (blockDim.x + 31) >> 5;
        float bmn = smn[0], bmx = smx[0];
        for (int k = 1; k < nwarps; k++) {
            bmn = fminf(bmn, smn[k]);
            bmx = fmaxf(bmx, smx[k]);
        }
        g_mn = bmn;
        g_mx = bmx;
    }
}

// Warp-tiled recurrence, 128-bit global I/O.
// Each warp owns 32 rows; k tiled in chunks of 32. Per chunk, the 32x32 fp32
// tile is moved as float4s: iteration t, lane l covers flat float4 index
// f = t*32 + l -> row = f/8, col4 = f%8 (lanes 0-7 = one row's 128B, 4 rows
// per warp instruction, perfectly coalesced LDG.128/STG.128).
// Smem scatter tile[row*33 + col4*4 + i] touches all 32 banks (row groups
// differ by 33===1 mod 32 -> distinct residues) -> conflict-free. Compute
// phase reads tile[lane*33 + kk] (stride 33 -> conflict-free).
__global__ void __launch_bounds__(WPB * 32) recur_kernel(
        const float* __restrict__ in,
        const float* __restrict__ alpha,
        const float* __restrict__ beta,
        float* __restrict__ out,
        int rows) {
    __shared__ float tile_s[WPB][32 * PITCH];

    const int lane = threadIdx.x & 31;
    const int warp = threadIdx.x >> 5;
    const int wgid = blockIdx.x * WPB + warp;
    if (wgid * 32 >= rows) return;

    float* tile = tile_s[warp];

    const float mn  = g_mn;
    const float rng = __fsub_rn(g_mx, mn);
    const float inv = __fdiv_rn(1.0f, rng);   // == div-by-rng bitwise (verified R2/R3)
    const float a   = alpha[0];
    const float nb  = -beta[0];

    const size_t base = (size_t)wgid * 32 * N_DIM;
    const float* __restrict__ inw  = in  + base;
    float* __restrict__       outw = out + base;

    // Per-lane (row, col4) decomposition for the float4 I/O pattern.
    const int my_col4x4 = (lane & 7) * 4;           // column offset within chunk
    // rows for t=0..7: t*4 + lane/8
    const int row_off = lane >> 3;

    // Prologue: load chunk 0 (LDG.128, coalesced).
    float4 q[8];
    #pragma unroll
    for (int t = 0; t < 8; t++) {
        int r = t * 4 + row_off;
        q[t] = *(const float4*)(inw + (size_t)r * N_DIM + my_col4x4);
    }

    float w = 1.0f;

    #pragma unroll 1
    for (int c = 0; c < NCHUNK; c++) {
        // Scatter current chunk regs -> smem (conflict-free).
        #pragma unroll
        for (int t = 0; t < 8; t++) {
            int r = t * 4 + row_off;
            float* p = tile + r * PITCH + my_col4x4;
            p[0] = q[t].x; p[1] = q[t].y; p[2] = q[t].z; p[3] = q[t].w;
        }
        __syncwarp();

        // Issue next chunk's LDG.128s; they overlap the compute below.
        if (c + 1 < NCHUNK) {
            const int k0n = (c + 1) * KCH;
            #pragma unroll
            for (int t = 0; t < 8; t++) {
                int r = t * 4 + row_off;
                q[t] = *(const float4*)(inw + (size_t)r * N_DIM + k0n + my_col4x4);
            }
        }

        // Serial recurrence: lane = row. out[:,k] is the pre-step w.
        //   xn = (x - mn) * inv ; w' = fma(-b, xn, w + (a / w))
        #pragma unroll
        for (int kk = 0; kk < KCH; kk++) {
            float x = tile[lane * PITCH + kk];
            tile[lane * PITCH + kk] = w;
            float xn = __fmul_rn(__fsub_rn(x, mn), inv);
            w = __fmaf_rn(nb, xn, __fadd_rn(w, __fdiv_rn(a, w)));
        }
        __syncwarp();

        // Gather w values from smem and store as STG.128 (coalesced).
        const int k0 = c * KCH;
        #pragma unroll
        for (int t = 0; t < 8; t++) {
            int r = t * 4 + row_off;
            const float* p = tile + r * PITCH + my_col4x4;
            float4 o;
            o.x = p[0]; o.y = p[1]; o.z = p[2]; o.w = p[3];
            *(float4*)(outw + (size_t)r * N_DIM + k0 + my_col4x4) = o;
        }
        __syncwarp();
    }
}

extern "C" void kernel_launch(void* const* d_in, const int* in_sizes, int n_in,
                              void* d_out, int out_size) {
    const float* in    = (const float*)d_in[0];
    const float* alpha = (const float*)d_in[1];
    const float* beta  = (const float*)d_in[2];
    float* out = (float*)d_out;

    long long n_elems = (long long)in_sizes[0];
    long long n4 = n_elems / 4;
    int rows = (int)(n_elems / N_DIM);

    minmax_kernel<<<MM_BLOCKS, 256>>>((const float4*)in, n4);
    reduce_minmax_kernel<<<1, 256>>>();

    int warps_needed = (rows + 31) / 32;
    int blocks = (warps_needed + WPB - 1) / WPB;
    recur_kernel<<<blocks, WPB * 32>>>(in, alpha, beta, out, rows);
}

// round 8
// speedup vs baseline: 1.0457x; 1.0431x over previous
#include <cuda_runtime.h>
#include <math_constants.h>

#define N_DIM 512
#define KCH 32            // k-chunk per tile pass
#define NCHUNK (N_DIM / KCH)
#define PITCH 33          // conflict-free for both scatter and compute phases
#define WPB 8             // warps per block
#define MM_BLOCKS 1184    // 8 * 148: exactly one wave
#define RC_BLOCKS 592     // 4 * 148: exactly 4 blocks per SM

// Device-global scratch (no allocations allowed). Partials are fully
// overwritten by minmax_kernel every call -> no init kernel needed.
__device__ float g_pmn[MM_BLOCKS];
__device__ float g_pmx[MM_BLOCKS];

__global__ void minmax_kernel(const float4* __restrict__ in, long long n4) {
    float mn0 =  CUDART_INF_F, mn1 =  CUDART_INF_F;
    float mn2 =  CUDART_INF_F, mn3 =  CUDART_INF_F;
    float mx0 = -CUDART_INF_F, mx1 = -CUDART_INF_F;
    float mx2 = -CUDART_INF_F, mx3 = -CUDART_INF_F;
    long long stride = (long long)gridDim.x * blockDim.x;
    long long i = (long long)blockIdx.x * blockDim.x + threadIdx.x;
    for (; i + 3 * stride < n4; i += 4 * stride) {
        float4 v0 = in[i];
        float4 v1 = in[i + stride];
        float4 v2 = in[i + 2 * stride];
        float4 v3 = in[i + 3 * stride];
        mn0 = fminf(mn0, fminf(fminf(v0.x, v0.y), fminf(v0.z, v0.w)));
        mx0 = fmaxf(mx0, fmaxf(fmaxf(v0.x, v0.y), fmaxf(v0.z, v0.w)));
        mn1 = fminf(mn1, fminf(fminf(v1.x, v1.y), fminf(v1.z, v1.w)));
        mx1 = fmaxf(mx1, fmaxf(fmaxf(v1.x, v1.y), fmaxf(v1.z, v1.w)));
        mn2 = fminf(mn2, fminf(fminf(v2.x, v2.y), fminf(v2.z, v2.w)));
        mx2 = fmaxf(mx2, fmaxf(fmaxf(v2.x, v2.y), fmaxf(v2.z, v2.w)));
        mn3 = fminf(mn3, fminf(fminf(v3.x, v3.y), fminf(v3.z, v3.w)));
        mx3 = fmaxf(mx3, fmaxf(fmaxf(v3.x, v3.y), fmaxf(v3.z, v3.w)));
    }
    for (; i < n4; i += stride) {
        float4 v = in[i];
        mn0 = fminf(mn0, fminf(fminf(v.x, v.y), fminf(v.z, v.w)));
        mx0 = fmaxf(mx0, fmaxf(fmaxf(v.x, v.y), fmaxf(v.z, v.w)));
    }
    float mn = fminf(fminf(mn0, mn1), fminf(mn2, mn3));
    float mx = fmaxf(fmaxf(mx0, mx1), fmaxf(mx2, mx3));
    #pragma unroll
    for (int o = 16; o > 0; o >>= 1) {
        mn = fminf(mn, __shfl_xor_sync(0xFFFFFFFFu, mn, o));
        mx = fmaxf(mx, __shfl_xor_sync(0xFFFFFFFFu, mx, o));
    }
    __shared__ float smn[32], smx[32];
    int warp = threadIdx.x >> 5;
    if ((threadIdx.x & 31) == 0) { smn[warp] = mn; smx[warp] = mx; }
    __syncthreads();
    if (threadIdx.x == 0) {
        int nwarps = (blockDim.x + 31) >> 5;
        float bmn = smn[0], bmx = smx[0];
        for (int k = 1; k < nwarps; k++) {
            bmn = fminf(bmn, smn[k]);
            bmx = fmaxf(bmx, smx[k]);
        }
        g_pmn[blockIdx.x] = bmn;   // deterministic overwrite, no atomics
        g_pmx[blockIdx.x] = bmx;
    }
}

// Warp-tiled recurrence, 128-bit global I/O, self-reducing prologue,
// balanced work distribution (each SM gets exactly 4 blocks; blocks carry
// 7 or 6 row-groups -> per-SM byte load uniform to ~1%).
__global__ void __launch_bounds__(WPB * 32) recur_kernel(
        const float* __restrict__ in,
        const float* __restrict__ alpha,
        const float* __restrict__ beta,
        float* __restrict__ out,
        int rows) {
    __shared__ float tile_s[WPB][32 * PITCH];
    __shared__ float s_red[64];
    __shared__ float s_mn, s_mx;

    const int tid  = threadIdx.x;
    const int lane = tid & 31;
    const int warp = tid >> 5;

    // ---- Prologue: every block reduces the 1184 minmax partials itself ----
    {
        float mn =  CUDART_INF_F;
        float mx = -CUDART_INF_F;
        for (int i = tid; i < MM_BLOCKS; i += WPB * 32) {
            mn = fminf(mn, g_pmn[i]);
            mx = fmaxf(mx, g_pmx[i]);
        }
        #pragma unroll
        for (int o = 16; o > 0; o >>= 1) {
            mn = fminf(mn, __shfl_xor_sync(0xFFFFFFFFu, mn, o));
            mx = fmaxf(mx, __shfl_xor_sync(0xFFFFFFFFu, mx, o));
        }
        if (lane == 0) { s_red[warp] = mn; s_red[32 + warp] = mx; }
        __syncthreads();
        if (tid == 0) {
            float bmn = s_red[0], bmx = s_red[32];
            #pragma unroll
            for (int k = 1; k < WPB; k++) {
                bmn = fminf(bmn, s_red[k]);
                bmx = fmaxf(bmx, s_red[32 + k]);
            }
            s_mn = bmn; s_mx = bmx;
        }
        __syncthreads();
    }

    // ---- Balanced group assignment: one 32-row group per active warp ----
    const int G    = rows >> 5;                     // total row-groups
    const int base = G / gridDim.x;
    const int rem  = G % gridDim.x;
    const int cnt  = base + (blockIdx.x < (unsigned)rem);
    const int strt = blockIdx.x * base + min((int)blockIdx.x, rem);
    if (warp >= cnt) return;
    const int wgid = strt + warp;

    float* tile = tile_s[warp];

    const float mn  = s_mn;
    const float rng = __fsub_rn(s_mx, mn);
    const float inv = __fdiv_rn(1.0f, rng);   // == div-by-rng bitwise (verified R2/R3)
    const float a   = alpha[0];
    const float nb  = -beta[0];

    const size_t bse = (size_t)wgid * 32 * N_DIM;
    const float* __restrict__ inw  = in  + bse;
    float* __restrict__       outw = out + bse;

    // float4 I/O pattern: lanes 0-7 = one row's 128B chunk, 4 rows per instr.
    const int my_col4x4 = (lane & 7) * 4;
    const int row_off   = lane >> 3;

    // Prologue: load chunk 0 (LDG.128, coalesced).
    float4 q[8];
    #pragma unroll
    for (int t = 0; t < 8; t++) {
        int r = t * 4 + row_off;
        q[t] = *(const float4*)(inw + (size_t)r * N_DIM + my_col4x4);
    }

    float w = 1.0f;

    #pragma unroll 1
    for (int c = 0; c < NCHUNK; c++) {
        // Scatter current chunk regs -> smem (conflict-free, pitch 33).
        #pragma unroll
        for (int t = 0; t < 8; t++) {
            int r = t * 4 + row_off;
            float* p = tile + r * PITCH + my_col4x4;
            p[0] = q[t].x; p[1] = q[t].y; p[2] = q[t].z; p[3] = q[t].w;
        }
        __syncwarp();

        // Issue next chunk's LDG.128s; they overlap the compute below.
        if (c + 1 < NCHUNK) {
            const int k0n = (c + 1) * KCH;
            #pragma unroll
            for (int t = 0; t < 8; t++) {
                int r = t * 4 + row_off;
                q[t] = *(const float4*)(inw + (size_t)r * N_DIM + k0n + my_col4x4);
            }
        }

        // Serial recurrence: lane = row. out[:,k] is the pre-step w.
        //   xn = (x - mn) * inv ; w' = fma(-b, xn, w + (a / w))
        #pragma unroll
        for (int kk = 0; kk < KCH; kk++) {
            float x = tile[lane * PITCH + kk];
            tile[lane * PITCH + kk] = w;
            float xn = __fmul_rn(__fsub_rn(x, mn), inv);
            w = __fmaf_rn(nb, xn, __fadd_rn(w, __fdiv_rn(a, w)));
        }
        __syncwarp();

        // Gather w values from smem and store as STG.128 (coalesced).
        const int k0 = c * KCH;
        #pragma unroll
        for (int t = 0; t < 8; t++) {
            int r = t * 4 + row_off;
            const float* p = tile + r * PITCH + my_col4x4;
            float4 o;
            o.x = p[0]; o.y = p[1]; o.z = p[2]; o.w = p[3];
            *(float4*)(outw + (size_t)r * N_DIM + k0 + my_col4x4) = o;
        }
        __syncwarp();
    }
}

extern "C" void kernel_launch(void* const* d_in, const int* in_sizes, int n_in,
                              void* d_out, int out_size) {
    const float* in    = (const float*)d_in[0];
    const float* alpha = (const float*)d_in[1];
    const float* beta  = (const float*)d_in[2];
    float* out = (float*)d_out;

    long long n_elems = (long long)in_sizes[0];
    long long n4 = n_elems / 4;
    int rows = (int)(n_elems / N_DIM);

    minmax_kernel<<<MM_BLOCKS, 256>>>((const float4*)in, n4);
    recur_kernel<<<RC_BLOCKS, WPB * 32>>>(in, alpha, beta, out, rows);
}